// round 1
// baseline (speedup 1.0000x reference)
#include <cuda_runtime.h>
#include <math.h>

// Problem constants
#define BB 4
#define TT 2048
#define CC 1024
#define HH 8
#define DD 128
#define NTOK (BB*TT)          // 8192

// ---------------------------------------------------------------------------
// Scratch (single static device buffer; no allocations anywhere)
// ---------------------------------------------------------------------------
#define XN_OFF  0
#define Q_OFF   (XN_OFF + (size_t)NTOK*CC)
#define K_OFF   (Q_OFF  + (size_t)NTOK*CC)
#define V_OFF   (K_OFF  + (size_t)NTOK*CC)
#define AO_OFF  (V_OFF  + (size_t)NTOK*CC)
#define QP_OFF  (AO_OFF + (size_t)NTOK*CC)
#define KP_OFF  (QP_OFF + (size_t)BB*HH*TT)
#define SCRATCH_TOTAL (KP_OFF + (size_t)BB*HH*TT)

__device__ float g_scratch[SCRATCH_TOTAL];

// ---------------------------------------------------------------------------
// LayerNorm: one block (256 thr) per token, float4 everywhere
// ---------------------------------------------------------------------------
__global__ __launch_bounds__(256) void ln_kernel(
    const float* __restrict__ x, const float* __restrict__ gam,
    const float* __restrict__ bet, float* __restrict__ xn)
{
    int row = blockIdx.x;
    int t   = threadIdx.x;
    const float4* xr = (const float4*)(x + (size_t)row * CC);
    float4 v = xr[t];
    float s  = v.x + v.y + v.z + v.w;
    float ss = v.x*v.x + v.y*v.y + v.z*v.z + v.w*v.w;
    #pragma unroll
    for (int o = 16; o; o >>= 1) {
        s  += __shfl_xor_sync(0xffffffffu, s,  o);
        ss += __shfl_xor_sync(0xffffffffu, ss, o);
    }
    __shared__ float ws[8], wss[8];
    int wid = t >> 5;
    if ((t & 31) == 0) { ws[wid] = s; wss[wid] = ss; }
    __syncthreads();
    s = 0.f; ss = 0.f;
    #pragma unroll
    for (int i = 0; i < 8; i++) { s += ws[i]; ss += wss[i]; }
    float mu  = s * (1.f / CC);
    float var = ss * (1.f / CC) - mu * mu;
    float inv = rsqrtf(var + 1e-5f);
    float4 g4 = ((const float4*)gam)[t];
    float4 b4 = ((const float4*)bet)[t];
    float4 o;
    o.x = (v.x - mu) * inv * g4.x + b4.x;
    o.y = (v.y - mu) * inv * g4.y + b4.y;
    o.z = (v.z - mu) * inv * g4.z + b4.z;
    o.w = (v.w - mu) * inv * g4.w + b4.w;
    ((float4*)(xn + (size_t)row * CC))[t] = o;
}

// ---------------------------------------------------------------------------
// TN GEMM:  Cm,n = sum_k A[m,k] * W[n,k]    (A,W row-major, K contiguous)
// 64x64 tile, BK=16, 256 threads, 4x4 micro-tile, float4 smem.
// MODE 0: scatter to head-major [B,H,T,D] (for q/k/v)
// MODE 1: out[m,n] = X[m,n] + acc          (final projection + residual)
// ---------------------------------------------------------------------------
template<int MODE>
__global__ __launch_bounds__(256) void gemm_tn(
    const float* __restrict__ A, const float* __restrict__ W,
    const float* __restrict__ X, float* __restrict__ out)
{
    __shared__ float As[64][20];
    __shared__ float Ws[64][20];
    int m0 = blockIdx.y << 6, n0 = blockIdx.x << 6;
    int tid = threadIdx.x, ty = tid >> 4, tx = tid & 15;
    int lr = tid >> 2, lc = (tid & 3) << 2;
    float acc[4][4] = {};
    const float* Ap = A + (size_t)(m0 + lr) * CC + lc;
    const float* Wp = W + (size_t)(n0 + lr) * CC + lc;
    for (int k0 = 0; k0 < CC; k0 += 16) {
        *(float4*)&As[lr][lc] = *(const float4*)(Ap + k0);
        *(float4*)&Ws[lr][lc] = *(const float4*)(Wp + k0);
        __syncthreads();
        #pragma unroll
        for (int kk = 0; kk < 16; kk += 4) {
            float4 aa[4], ww[4];
            #pragma unroll
            for (int r = 0; r < 4; r++) aa[r] = *(float4*)&As[ty*4 + r][kk];
            #pragma unroll
            for (int c = 0; c < 4; c++) ww[c] = *(float4*)&Ws[tx + 16*c][kk];
            #pragma unroll
            for (int r = 0; r < 4; r++)
                #pragma unroll
                for (int c = 0; c < 4; c++)
                    acc[r][c] += aa[r].x*ww[c].x + aa[r].y*ww[c].y
                               + aa[r].z*ww[c].z + aa[r].w*ww[c].w;
        }
        __syncthreads();
    }
    #pragma unroll
    for (int r = 0; r < 4; r++) {
        int m = m0 + ty*4 + r;
        #pragma unroll
        for (int c = 0; c < 4; c++) {
            int n = n0 + tx + 16*c;
            if (MODE == 0) {
                int b = m >> 11, t = m & 2047, h = n >> 7, d = n & 127;
                out[(((size_t)(b*HH + h) * TT) + t) * DD + d] = acc[r][c];
            } else {
                out[(size_t)m * CC + n] = X[(size_t)m * CC + n] + acc[r][c];
            }
        }
    }
}

// ---------------------------------------------------------------------------
// RoPE on q,k (head-major layout) + geo projections qp,kp
// one block = one (b,h,t); threads 0..63 -> q pairs, 64..127 -> k pairs
// ---------------------------------------------------------------------------
__global__ __launch_bounds__(128) void rope_kernel(
    float* __restrict__ q, float* __restrict__ k,
    const float* __restrict__ dirs,
    float* __restrict__ qp, float* __restrict__ kp)
{
    int idx = blockIdx.x;                  // (b*H+h)*T + t
    int t = idx & (TT - 1);
    int h = (idx >> 11) & (HH - 1);
    int tid = threadIdx.x;
    int i = tid & 63;
    float* p = (tid < 64 ? q : k) + (size_t)idx * DD;
    float x1 = p[i], x2 = p[i + 64];
    // inv = 10000^(-i/64)
    float inv = expf(-9.210340371976184f * (float)i * (1.f / 64.f));
    float ang = (float)t * inv;
    float sn, cs;
    sincosf(ang, &sn, &cs);
    float y1 = x1 * cs - x2 * sn;
    float y2 = x2 * cs + x1 * sn;
    p[i] = y1;
    p[i + 64] = y2;
    __shared__ float red[6];
    if (i < 3) red[(tid >> 6) * 3 + i] = y1 * dirs[h * 3 + i];
    __syncthreads();
    if (tid == 0)  qp[idx] = red[0] + red[1] + red[2];
    if (tid == 64) kp[idx] = red[3] + red[4] + red[5];
}

// ---------------------------------------------------------------------------
// Dual flash attention (regular softmax + rank-1 geo softmax, shared V)
// block = 64 queries x D=128, 256 threads. Streams 64-key tiles.
// ---------------------------------------------------------------------------
#define QP_PAD 132      // padded row (floats) for Q/K/V tiles
#define PP_PAD 68       // padded row for P tiles
#define ATTN_SMEM ((3*64*QP_PAD + 2*64*PP_PAD + 128) * 4)

__global__ __launch_bounds__(256) void attn_kernel(
    const float* __restrict__ q, const float* __restrict__ k,
    const float* __restrict__ v, const float* __restrict__ qp,
    const float* __restrict__ kp, const float* __restrict__ head_scales,
    float* __restrict__ out)
{
    extern __shared__ float sm[];
    float* Qs  = sm;                        // [64][132]
    float* Ks  = Qs + 64*QP_PAD;            // [64][132]
    float* Vs  = Ks + 64*QP_PAD;            // [64][132]
    float* Ps  = Vs + 64*QP_PAD;            // [64][68]
    float* Pg  = Ps + 64*PP_PAD;            // [64][68]
    float* qps = Pg + 64*PP_PAD;            // [64]
    float* kps = qps + 64;                  // [64]

    int bh = blockIdx.y;
    int b = bh >> 3, h = bh & 7;
    int q0 = blockIdx.x << 6;
    size_t base = (size_t)bh * TT * DD;
    int tid = threadIdx.x, ty = tid >> 4, tx = tid & 15;

    for (int idx = tid; idx < 64*32; idx += 256) {
        int r = idx >> 5, d4 = (idx & 31) << 2;
        *(float4*)&Qs[r*QP_PAD + d4] =
            *(const float4*)&q[base + (size_t)(q0 + r)*DD + d4];
    }
    if (tid < 64) qps[tid] = qp[(size_t)bh*TT + q0 + tid];

    float m[4], l[4], mg[4], lg[4];
    float O[4][8] = {}, Og[4][8] = {};
    #pragma unroll
    for (int r = 0; r < 4; r++) { m[r] = -INFINITY; l[r] = 0.f; mg[r] = -INFINITY; lg[r] = 0.f; }
    float hs = head_scales[h];
    const float scale = 0.08838834764831845f;   // 1/sqrt(128)

    #pragma unroll 1
    for (int n0 = 0; n0 <= q0; n0 += 64) {
        __syncthreads();        // protects Vs/Ps of previous iteration & Q on first
        for (int idx = tid; idx < 64*32; idx += 256) {
            int r = idx >> 5, d4 = (idx & 31) << 2;
            *(float4*)&Ks[r*QP_PAD + d4] =
                *(const float4*)&k[base + (size_t)(n0 + r)*DD + d4];
            *(float4*)&Vs[r*QP_PAD + d4] =
                *(const float4*)&v[base + (size_t)(n0 + r)*DD + d4];
        }
        if (tid < 64) kps[tid] = kp[(size_t)bh*TT + n0 + tid];
        __syncthreads();

        // ---- S = Q @ K^T  (64x64), 4x4 per thread
        float s[4][4] = {};
        #pragma unroll 8
        for (int kk = 0; kk < DD; kk += 4) {
            float4 aa[4], bk[4];
            #pragma unroll
            for (int r = 0; r < 4; r++) aa[r] = *(float4*)&Qs[(ty*4 + r)*QP_PAD + kk];
            #pragma unroll
            for (int c = 0; c < 4; c++) bk[c] = *(float4*)&Ks[(tx + 16*c)*QP_PAD + kk];
            #pragma unroll
            for (int r = 0; r < 4; r++)
                #pragma unroll
                for (int c = 0; c < 4; c++)
                    s[r][c] += aa[r].x*bk[c].x + aa[r].y*bk[c].y
                             + aa[r].z*bk[c].z + aa[r].w*bk[c].w;
        }

        bool diag = (n0 == q0);
        // ---- online softmax (attn + geo) per row
        #pragma unroll
        for (int r = 0; r < 4; r++) {
            int row = ty*4 + r;
            // attn
            float sv[4], mloc = -INFINITY;
            #pragma unroll
            for (int c = 0; c < 4; c++) {
                int col = tx + 16*c;
                float x_ = s[r][c] * scale;
                if (diag && col > row) x_ = -INFINITY;
                sv[c] = x_;
                mloc = fmaxf(mloc, x_);
            }
            #pragma unroll
            for (int o = 8; o; o >>= 1)
                mloc = fmaxf(mloc, __shfl_xor_sync(0xffffffffu, mloc, o, 16));
            float mn = fmaxf(m[r], mloc);
            float alpha = expf(m[r] - mn);
            float rsum = 0.f;
            #pragma unroll
            for (int c = 0; c < 4; c++) {
                float p_ = expf(sv[c] - mn);
                Ps[row*PP_PAD + tx + 16*c] = p_;
                rsum += p_;
            }
            #pragma unroll
            for (int o = 8; o; o >>= 1)
                rsum += __shfl_xor_sync(0xffffffffu, rsum, o, 16);
            l[r] = l[r]*alpha + rsum;
            m[r] = mn;
            #pragma unroll
            for (int c = 0; c < 8; c++) O[r][c] *= alpha;

            // geo (rank-1 scores)
            float qpr = qps[row];
            float gv[4], gloc = -INFINITY;
            #pragma unroll
            for (int c = 0; c < 4; c++) {
                int col = tx + 16*c;
                float g_ = qpr * kps[col];
                if (diag && col > row) g_ = -INFINITY;
                gv[c] = g_;
                gloc = fmaxf(gloc, g_);
            }
            #pragma unroll
            for (int o = 8; o; o >>= 1)
                gloc = fmaxf(gloc, __shfl_xor_sync(0xffffffffu, gloc, o, 16));
            float gmn = fmaxf(mg[r], gloc);
            float galpha = expf(mg[r] - gmn);
            float gsum = 0.f;
            #pragma unroll
            for (int c = 0; c < 4; c++) {
                float p_ = expf(gv[c] - gmn);
                Pg[row*PP_PAD + tx + 16*c] = p_;
                gsum += p_;
            }
            #pragma unroll
            for (int o = 8; o; o >>= 1)
                gsum += __shfl_xor_sync(0xffffffffu, gsum, o, 16);
            lg[r] = lg[r]*galpha + gsum;
            mg[r] = gmn;
            #pragma unroll
            for (int c = 0; c < 8; c++) Og[r][c] *= galpha;
        }
        __syncthreads();

        // ---- O += P @ V ; Og += Pg @ V
        #pragma unroll 4
        for (int n = 0; n < 64; n++) {
            float vv[8];
            #pragma unroll
            for (int c = 0; c < 8; c++) vv[c] = Vs[n*QP_PAD + tx + 16*c];
            #pragma unroll
            for (int r = 0; r < 4; r++) {
                float pr  = Ps[(ty*4 + r)*PP_PAD + n];
                float pgr = Pg[(ty*4 + r)*PP_PAD + n];
                #pragma unroll
                for (int c = 0; c < 8; c++) {
                    O[r][c]  += pr  * vv[c];
                    Og[r][c] += pgr * vv[c];
                }
            }
        }
    }

    // ---- epilogue: normalize, blend, write (b,t,c) layout
    #pragma unroll
    for (int r = 0; r < 4; r++) {
        int row = q0 + ty*4 + r;
        float invl  = 1.f / l[r];
        float invlg = 1.f / lg[r];
        #pragma unroll
        for (int c = 0; c < 8; c++) {
            float o  = O[r][c]  * invl;
            float og = Og[r][c] * invlg;
            float val = o + hs * (og - o);
            out[(size_t)(b*TT + row)*CC + h*DD + tx + 16*c] = val;
        }
    }
}

// ---------------------------------------------------------------------------
// Launcher
// ---------------------------------------------------------------------------
extern "C" void kernel_launch(void* const* d_in, const int* in_sizes, int n_in,
                              void* d_out, int out_size)
{
    const float* x   = (const float*)d_in[0];
    const float* Wq  = (const float*)d_in[1];
    const float* Wk  = (const float*)d_in[2];
    const float* Wv  = (const float*)d_in[3];
    const float* Wo  = (const float*)d_in[4];
    const float* lng = (const float*)d_in[5];
    const float* lnb = (const float*)d_in[6];
    const float* hsc = (const float*)d_in[7];
    const float* hdr = (const float*)d_in[8];
    float* out = (float*)d_out;

    float* base = nullptr;
    cudaGetSymbolAddress((void**)&base, g_scratch);
    float* xn = base + XN_OFF;
    float* gq = base + Q_OFF;
    float* gk = base + K_OFF;
    float* gv = base + V_OFF;
    float* ao = base + AO_OFF;
    float* gqp = base + QP_OFF;
    float* gkp = base + KP_OFF;

    ln_kernel<<<NTOK, 256>>>(x, lng, lnb, xn);

    dim3 gg(CC / 64, NTOK / 64);
    gemm_tn<0><<<gg, 256>>>(xn, Wq, nullptr, gq);
    gemm_tn<0><<<gg, 256>>>(xn, Wk, nullptr, gk);
    gemm_tn<0><<<gg, 256>>>(xn, Wv, nullptr, gv);

    rope_kernel<<<BB*HH*TT, 128>>>(gq, gk, hdr, gqp, gkp);

    cudaFuncSetAttribute(attn_kernel,
                         cudaFuncAttributeMaxDynamicSharedMemorySize, ATTN_SMEM);
    attn_kernel<<<dim3(TT/64, BB*HH), 256, ATTN_SMEM>>>(gq, gk, gv, gqp, gkp, hsc, ao);

    gemm_tn<1><<<gg, 256>>>(ao, Wo, x, out);
}